// round 4
// baseline (speedup 1.0000x reference)
#include <cuda_runtime.h>

#define N_FEAT 292
#define HID 256
#define TILE 16
#define PAD 20
#define SMEM_FLOATS (N_FEAT*PAD + 3*HID*PAD)
#define SMEM_BYTES (SMEM_FLOATS * 4)

// -------- gamma/beta-folded, transposed weights ([k][n] layout) ----------
__device__ float g_A1v[N_FEAT*HID];
__device__ float g_A1p[N_FEAT*HID];
__device__ float g_A2v[HID*HID];
__device__ float g_A2p[HID*HID];
__device__ float g_c1v[HID], g_c1p[HID], g_c2v[HID], g_c2p[HID];
__device__ float g_a3v[HID];
__device__ float g_A3p[HID*10];
__device__ float g_c3v;
__device__ float g_c3p[10];

// ---------------------------------------------------------------------------
// Prep: A[k][n] = W[n][k] * gamma[k]; c[n] = b[n] + sum_k W[n][k]*beta[k]
// One kernel, 1025 blocks: [0,512) layer1, [512,1024) layer2, 1024 layer3.
// ---------------------------------------------------------------------------
__global__ void prep_kernel(
    const float* __restrict__ ln1_w, const float* __restrict__ ln1_b,
    const float* __restrict__ ln2_w, const float* __restrict__ ln2_b,
    const float* __restrict__ ln3_w, const float* __restrict__ ln3_b,
    const float* __restrict__ n1g,  const float* __restrict__ n1b,
    const float* __restrict__ n2g,  const float* __restrict__ n2b,
    const float* __restrict__ n3g,  const float* __restrict__ n3b,
    const float* __restrict__ p1w,  const float* __restrict__ p1b,
    const float* __restrict__ p2w,  const float* __restrict__ p2b,
    const float* __restrict__ p3w,  const float* __restrict__ p3b,
    const float* __restrict__ pn1g, const float* __restrict__ pn1b,
    const float* __restrict__ pn2g, const float* __restrict__ pn2b,
    const float* __restrict__ pn3g, const float* __restrict__ pn3b)
{
    __shared__ float red[256];
    const int b = blockIdx.x, t = threadIdx.x;

    if (b < 512) {
        const int tower = b >> 8, n = b & 255;
        const float* W  = tower ? p1w  : ln1_w;
        const float* bi = tower ? p1b  : ln1_b;
        const float* g  = tower ? pn1g : n1g;
        const float* be = tower ? pn1b : n1b;
        float* A = tower ? g_A1p : g_A1v;
        float* c = tower ? g_c1p : g_c1v;
        float s = 0.f;
        for (int k = t; k < N_FEAT; k += 256) {
            float w = W[n*N_FEAT + k];
            A[k*HID + n] = w * g[k];
            s += w * be[k];
        }
        red[t] = s; __syncthreads();
        for (int o = 128; o > 0; o >>= 1) { if (t < o) red[t] += red[t+o]; __syncthreads(); }
        if (t == 0) c[n] = bi[n] + red[0];
    } else if (b < 1024) {
        const int idx = b - 512;
        const int tower = idx >> 8, n = idx & 255;
        const float* W  = tower ? p2w  : ln2_w;
        const float* bi = tower ? p2b  : ln2_b;
        const float* g  = tower ? pn2g : n2g;
        const float* be = tower ? pn2b : n2b;
        float* A = tower ? g_A2p : g_A2v;
        float* c = tower ? g_c2p : g_c2v;
        float w = W[n*HID + t];
        A[t*HID + n] = w * g[t];
        red[t] = w * be[t]; __syncthreads();
        for (int o = 128; o > 0; o >>= 1) { if (t < o) red[t] += red[t+o]; __syncthreads(); }
        if (t == 0) c[n] = bi[n] + red[0];
    } else {
        // layer 3 (value: 256->1, prob: 256->10)
        float w3 = ln3_w[t];
        g_a3v[t] = w3 * n3g[t];
        red[t] = w3 * n3b[t]; __syncthreads();
        for (int o = 128; o > 0; o >>= 1) { if (t < o) red[t] += red[t+o]; __syncthreads(); }
        if (t == 0) g_c3v = ln3_b[0] + red[0];
        __syncthreads();
        #pragma unroll
        for (int j = 0; j < 10; j++)
            g_A3p[t*10 + j] = p3w[j*HID + t] * pn3g[t];
        for (int j = 0; j < 10; j++) {
            red[t] = p3w[j*HID + t] * pn3b[t]; __syncthreads();
            for (int o = 128; o > 0; o >>= 1) { if (t < o) red[t] += red[t+o]; __syncthreads(); }
            if (t == 0) g_c3p[j] = p3b[j] + red[0];
            __syncthreads();
        }
    }
}

// ---------------------------------------------------------------------------
// Main fused kernel
// ---------------------------------------------------------------------------
__device__ __forceinline__ void ln_rows(float* z, int K, int lane, int r) {
    float s = 0.f, ss = 0.f;
    for (int k = lane; k < K; k += 16) {
        float x = z[k*PAD + r];
        s += x; ss += x * x;
    }
    #pragma unroll
    for (int o = 8; o; o >>= 1) {
        s  += __shfl_xor_sync(0xffffffffu, s,  o, 16);
        ss += __shfl_xor_sync(0xffffffffu, ss, o, 16);
    }
    const float inv = 1.f / (float)K;
    float m    = s * inv;
    float var  = fmaxf(ss * inv - m*m, 0.f);
    float rstd = rsqrtf(var + 1e-5f);
    for (int k = lane; k < K; k += 16)
        z[k*PAD + r] = (z[k*PAD + r] - m) * rstd;
}

// fma16: acc[0..15] += z[0..15] * weight.  Inline function (NOT a macro) so
// float4 member names cannot be captured by parameter names.
__device__ __forceinline__ void fma16(float* acc,
                                      const float4& va, const float4& vb,
                                      const float4& vc, const float4& vd,
                                      float wgt)
{
    acc[0]  = fmaf(va.x, wgt, acc[0]);  acc[1]  = fmaf(va.y, wgt, acc[1]);
    acc[2]  = fmaf(va.z, wgt, acc[2]);  acc[3]  = fmaf(va.w, wgt, acc[3]);
    acc[4]  = fmaf(vb.x, wgt, acc[4]);  acc[5]  = fmaf(vb.y, wgt, acc[5]);
    acc[6]  = fmaf(vb.z, wgt, acc[6]);  acc[7]  = fmaf(vb.w, wgt, acc[7]);
    acc[8]  = fmaf(vc.x, wgt, acc[8]);  acc[9]  = fmaf(vc.y, wgt, acc[9]);
    acc[10] = fmaf(vc.z, wgt, acc[10]); acc[11] = fmaf(vc.w, wgt, acc[11]);
    acc[12] = fmaf(vd.x, wgt, acc[12]); acc[13] = fmaf(vd.y, wgt, acc[13]);
    acc[14] = fmaf(vd.z, wgt, acc[14]); acc[15] = fmaf(vd.w, wgt, acc[15]);
}

__global__ __launch_bounds__(256, 2) void bcq_main(
    const float* __restrict__ cum, const float* __restrict__ feat,
    const float* __restrict__ pos, float* __restrict__ out, int N)
{
    extern __shared__ float sm[];
    float* z1  = sm;                    // [292][PAD]; reused later as z3v
    float* z2v = sm + N_FEAT*PAD;       // [256][PAD]
    float* z2p = z2v + HID*PAD;
    float* z3p = z2p + HID*PAD;
    float* z3v = z1;

    const int t    = threadIdx.x;
    const int lane = t & 15;
    const int grp  = t >> 4;            // row within tile
    const long rowBase = (long)blockIdx.x * TILE;
    const long rowG    = rowBase + grp;
    const long rowLd   = rowG < N ? rowG : (long)N - 1;   // clamp for loads
    const bool rowOk   = rowG < N;

    // ---- load x tile (transposed into smem) + LN1 (standardize only) ----
    {
        const float* c0 = cum  + rowLd * 146;
        const float* f0 = feat + rowLd * 136;
        const float* p0 = pos  + rowLd * 10;
        float s = 0.f, ss = 0.f;
        for (int k = lane; k < N_FEAT; k += 16) {
            float x;
            if (k < 146)      x = c0[k];
            else if (k < 282) x = f0[k - 146];
            else              x = p0[k - 282];
            z1[k*PAD + grp] = x;
            s += x; ss += x * x;
        }
        #pragma unroll
        for (int o = 8; o; o >>= 1) {
            s  += __shfl_xor_sync(0xffffffffu, s,  o, 16);
            ss += __shfl_xor_sync(0xffffffffu, ss, o, 16);
        }
        const float inv = 1.f / (float)N_FEAT;
        float m    = s * inv;
        float var  = fmaxf(ss * inv - m*m, 0.f);
        float rstd = rsqrtf(var + 1e-5f);
        for (int k = lane; k < N_FEAT; k += 16)
            z1[k*PAD + grp] = (z1[k*PAD + grp] - m) * rstd;
    }
    __syncthreads();

    // ---- GEMM1: [16 x 292] @ [292 x 512] (both towers share z1) ----
    {
        float av[16], ap[16];
        #pragma unroll
        for (int i = 0; i < 16; i++) { av[i] = 0.f; ap[i] = 0.f; }
        const float* Av = g_A1v + t;
        const float* Ap = g_A1p + t;
        #pragma unroll 2
        for (int k = 0; k < N_FEAT; k++) {
            float wv = Av[k*HID];
            float wp = Ap[k*HID];
            const float4* zb = (const float4*)(z1 + k*PAD);
            float4 va = zb[0], vb = zb[1], vc = zb[2], vd = zb[3];
            fma16(av, va, vb, vc, vd, wv);
            fma16(ap, va, vb, vc, vd, wp);
        }
        const float b1v = g_c1v[t], b1p = g_c1p[t];
        #pragma unroll
        for (int r = 0; r < 16; r++) {
            z2v[t*PAD + r] = fmaxf(av[r] + b1v, 0.f);
            z2p[t*PAD + r] = fmaxf(ap[r] + b1p, 0.f);
        }
    }
    __syncthreads();

    ln_rows(z2v, HID, lane, grp);
    ln_rows(z2p, HID, lane, grp);
    __syncthreads();

    // ---- GEMM2: [16 x 256] @ [256 x 512] (per-tower activations) ----
    {
        float av[16], ap[16];
        #pragma unroll
        for (int i = 0; i < 16; i++) { av[i] = 0.f; ap[i] = 0.f; }
        const float* Av = g_A2v + t;
        const float* Ap = g_A2p + t;
        #pragma unroll 2
        for (int k = 0; k < HID; k++) {
            float wv = Av[k*HID];
            float wp = Ap[k*HID];
            {
                const float4* zb = (const float4*)(z2v + k*PAD);
                float4 va = zb[0], vb = zb[1], vc = zb[2], vd = zb[3];
                fma16(av, va, vb, vc, vd, wv);
            }
            {
                const float4* zb = (const float4*)(z2p + k*PAD);
                float4 va = zb[0], vb = zb[1], vc = zb[2], vd = zb[3];
                fma16(ap, va, vb, vc, vd, wp);
            }
        }
        const float b2v = g_c2v[t], b2p = g_c2p[t];
        // z3v aliases z1: z1 reads all completed before the post-GEMM1 barrier
        #pragma unroll
        for (int r = 0; r < 16; r++) {
            z3v[t*PAD + r] = fmaxf(av[r] + b2v, 0.f);
            z3p[t*PAD + r] = fmaxf(ap[r] + b2p, 0.f);
        }
    }
    __syncthreads();

    ln_rows(z3v, HID, lane, grp);
    ln_rows(z3p, HID, lane, grp);
    __syncthreads();

    // ---- heads: value = a3.z3v + c3 ; score = A3p^T z3p ; log_softmax ----
    {
        // value head
        float s = 0.f;
        for (int k = lane; k < HID; k += 16)
            s += g_a3v[k] * z3v[k*PAD + grp];
        #pragma unroll
        for (int o = 8; o; o >>= 1)
            s += __shfl_xor_sync(0xffffffffu, s, o, 16);

        // prob head: 10 logits
        float acc[10];
        #pragma unroll
        for (int j = 0; j < 10; j++) acc[j] = 0.f;
        for (int k = lane; k < HID; k += 16) {
            float z = z3p[k*PAD + grp];
            #pragma unroll
            for (int j = 0; j < 10; j++)
                acc[j] = fmaf(z, g_A3p[k*10 + j], acc[j]);
        }
        #pragma unroll
        for (int j = 0; j < 10; j++) {
            #pragma unroll
            for (int o = 8; o; o >>= 1)
                acc[j] += __shfl_xor_sync(0xffffffffu, acc[j], o, 16);
        }

        if (lane == 0 && rowOk) {
            out[rowG] = s + g_c3v;                     // value [N]
            float sc[10];
            float mx = -3.4e38f;
            #pragma unroll
            for (int j = 0; j < 10; j++) {
                sc[j] = acc[j] + g_c3p[j];
                mx = fmaxf(mx, sc[j]);
            }
            float se = 0.f;
            #pragma unroll
            for (int j = 0; j < 10; j++) se += expf(sc[j] - mx);
            float lse = mx + logf(se);
            float* lp = out + N + rowG * 10;           // log_prob [N,10]
            float* so = out + N + (long)N * 10 + rowG * 10;  // score [N,10]
            #pragma unroll
            for (int j = 0; j < 10; j++) {
                lp[j] = sc[j] - lse;
                so[j] = sc[j];
            }
        }
    }
}

// ---------------------------------------------------------------------------
extern "C" void kernel_launch(void* const* d_in, const int* in_sizes, int n_in,
                              void* d_out, int out_size) {
    const float* cum  = (const float*)d_in[0];
    const float* feat = (const float*)d_in[1];
    const float* pos  = (const float*)d_in[2];
    const int N = in_sizes[0] / 146;

    cudaFuncSetAttribute(bcq_main, cudaFuncAttributeMaxDynamicSharedMemorySize, SMEM_BYTES);

    prep_kernel<<<1025, 256>>>(
        (const float*)d_in[3],  (const float*)d_in[4],   // ln1_w, ln1_b
        (const float*)d_in[5],  (const float*)d_in[6],   // ln2_w, ln2_b
        (const float*)d_in[7],  (const float*)d_in[8],   // ln3_w, ln3_b
        (const float*)d_in[9],  (const float*)d_in[10],  // norm1_g, norm1_b
        (const float*)d_in[11], (const float*)d_in[12],  // norm2_g, norm2_b
        (const float*)d_in[13], (const float*)d_in[14],  // norm3_g, norm3_b
        (const float*)d_in[15], (const float*)d_in[16],  // prob1_w, prob1_b
        (const float*)d_in[17], (const float*)d_in[18],  // prob2_w, prob2_b
        (const float*)d_in[19], (const float*)d_in[20],  // prob3_w, prob3_b
        (const float*)d_in[21], (const float*)d_in[22],  // pnorm1_g, pnorm1_b
        (const float*)d_in[23], (const float*)d_in[24],  // pnorm2_g, pnorm2_b
        (const float*)d_in[25], (const float*)d_in[26]); // pnorm3_g, pnorm3_b

    const int grid = (N + TILE - 1) / TILE;
    bcq_main<<<grid, 256, SMEM_BYTES>>>(cum, feat, pos, (float*)d_out, N);
}

// round 5
// speedup vs baseline: 1.4713x; 1.4713x over previous
#include <cuda_runtime.h>

#define N_FEAT 292
#define HID 256
#define TILE 16
#define PAD 20
#define SMEM_FLOATS (N_FEAT*PAD + 3*HID*PAD)
#define SMEM_BYTES (SMEM_FLOATS * 4)

// -------- gamma/beta-folded weights --------------------------------------
// A1/A2 are stored k-packed: A[((k>>2)*HID + n)*4 + (k&3)]  so one LDG.128
// per thread fetches the 4 consecutive-k weights of its column n.
__device__ float g_A1v[N_FEAT*HID];
__device__ float g_A1p[N_FEAT*HID];
__device__ float g_A2v[HID*HID];
__device__ float g_A2p[HID*HID];
__device__ float g_c1v[HID], g_c1p[HID], g_c2v[HID], g_c2p[HID];
__device__ float g_a3v[HID];
__device__ float g_A3p[HID*10];
__device__ float g_c3v;
__device__ float g_c3p[10];

// ---------------------------------------------------------------------------
// f32x2 helpers (FFMA2 is only reachable via PTX fma.rn.f32x2)
// ---------------------------------------------------------------------------
__device__ __forceinline__ unsigned long long pack2(float w) {
    unsigned long long r;
    asm("mov.b64 %0, {%1, %1};" : "=l"(r) : "f"(w));
    return r;
}
__device__ __forceinline__ void unpack2(unsigned long long v, float& lo, float& hi) {
    asm("mov.b64 {%0, %1}, %2;" : "=f"(lo), "=f"(hi) : "l"(v));
}
__device__ __forceinline__ void fma2(unsigned long long& acc,
                                     unsigned long long z, unsigned long long w) {
    asm("fma.rn.f32x2 %0, %1, %2, %0;" : "+l"(acc) : "l"(z), "l"(w));
}

// ---------------------------------------------------------------------------
// Prep: A[k][n] = W[n][k]*gamma[k] (k-packed layout); c[n] = b[n]+sum W[n][k]*beta[k]
// ---------------------------------------------------------------------------
__global__ void prep_kernel(
    const float* __restrict__ ln1_w, const float* __restrict__ ln1_b,
    const float* __restrict__ ln2_w, const float* __restrict__ ln2_b,
    const float* __restrict__ ln3_w, const float* __restrict__ ln3_b,
    const float* __restrict__ n1g,  const float* __restrict__ n1b,
    const float* __restrict__ n2g,  const float* __restrict__ n2b,
    const float* __restrict__ n3g,  const float* __restrict__ n3b,
    const float* __restrict__ p1w,  const float* __restrict__ p1b,
    const float* __restrict__ p2w,  const float* __restrict__ p2b,
    const float* __restrict__ p3w,  const float* __restrict__ p3b,
    const float* __restrict__ pn1g, const float* __restrict__ pn1b,
    const float* __restrict__ pn2g, const float* __restrict__ pn2b,
    const float* __restrict__ pn3g, const float* __restrict__ pn3b)
{
    __shared__ float red[256];
    const int b = blockIdx.x, t = threadIdx.x;

    if (b < 512) {
        const int tower = b >> 8, n = b & 255;
        const float* W  = tower ? p1w  : ln1_w;
        const float* bi = tower ? p1b  : ln1_b;
        const float* g  = tower ? pn1g : n1g;
        const float* be = tower ? pn1b : n1b;
        float* A = tower ? g_A1p : g_A1v;
        float* c = tower ? g_c1p : g_c1v;
        float s = 0.f;
        for (int k = t; k < N_FEAT; k += 256) {
            float w = W[n*N_FEAT + k];
            A[((k>>2)*HID + n)*4 + (k&3)] = w * g[k];
            s += w * be[k];
        }
        red[t] = s; __syncthreads();
        for (int o = 128; o > 0; o >>= 1) { if (t < o) red[t] += red[t+o]; __syncthreads(); }
        if (t == 0) c[n] = bi[n] + red[0];
    } else if (b < 1024) {
        const int idx = b - 512;
        const int tower = idx >> 8, n = idx & 255;
        const float* W  = tower ? p2w  : ln2_w;
        const float* bi = tower ? p2b  : ln2_b;
        const float* g  = tower ? pn2g : n2g;
        const float* be = tower ? pn2b : n2b;
        float* A = tower ? g_A2p : g_A2v;
        float* c = tower ? g_c2p : g_c2v;
        float w = W[n*HID + t];
        A[((t>>2)*HID + n)*4 + (t&3)] = w * g[t];
        red[t] = w * be[t]; __syncthreads();
        for (int o = 128; o > 0; o >>= 1) { if (t < o) red[t] += red[t+o]; __syncthreads(); }
        if (t == 0) c[n] = bi[n] + red[0];
    } else {
        float w3 = ln3_w[t];
        g_a3v[t] = w3 * n3g[t];
        red[t] = w3 * n3b[t]; __syncthreads();
        for (int o = 128; o > 0; o >>= 1) { if (t < o) red[t] += red[t+o]; __syncthreads(); }
        if (t == 0) g_c3v = ln3_b[0] + red[0];
        __syncthreads();
        #pragma unroll
        for (int j = 0; j < 10; j++)
            g_A3p[t*10 + j] = p3w[j*HID + t] * pn3g[t];
        for (int j = 0; j < 10; j++) {
            red[t] = p3w[j*HID + t] * pn3b[t]; __syncthreads();
            for (int o = 128; o > 0; o >>= 1) { if (t < o) red[t] += red[t+o]; __syncthreads(); }
            if (t == 0) g_c3p[j] = p3b[j] + red[0];
            __syncthreads();
        }
    }
}

// ---------------------------------------------------------------------------
// Main fused kernel
// ---------------------------------------------------------------------------
__device__ __forceinline__ void ln_rows(float* z, int K, int lane, int r) {
    float s = 0.f, ss = 0.f;
    for (int k = lane; k < K; k += 16) {
        float x = z[k*PAD + r];
        s += x; ss += x * x;
    }
    #pragma unroll
    for (int o = 8; o; o >>= 1) {
        s  += __shfl_xor_sync(0xffffffffu, s,  o, 16);
        ss += __shfl_xor_sync(0xffffffffu, ss, o, 16);
    }
    const float inv = 1.f / (float)K;
    float m    = s * inv;
    float var  = fmaxf(ss * inv - m*m, 0.f);
    float rstd = rsqrtf(var + 1e-5f);
    for (int k = lane; k < K; k += 16)
        z[k*PAD + r] = (z[k*PAD + r] - m) * rstd;
}

// 8 packed FMAs: acc2[0..7] (16 rows) += zrow * w2
__device__ __forceinline__ void fma2x8(unsigned long long* acc2,
                                       const float* zrow, unsigned long long w2) {
    const ulonglong2* zr = (const ulonglong2*)zrow;
    ulonglong2 z01 = zr[0], z23 = zr[1], z45 = zr[2], z67 = zr[3];
    fma2(acc2[0], z01.x, w2); fma2(acc2[1], z01.y, w2);
    fma2(acc2[2], z23.x, w2); fma2(acc2[3], z23.y, w2);
    fma2(acc2[4], z45.x, w2); fma2(acc2[5], z45.y, w2);
    fma2(acc2[6], z67.x, w2); fma2(acc2[7], z67.y, w2);
}

__global__ __launch_bounds__(256, 2) void bcq_main(
    const float* __restrict__ cum, const float* __restrict__ feat,
    const float* __restrict__ pos, float* __restrict__ out, int N)
{
    extern __shared__ float sm[];
    float* z1  = sm;                    // [292][PAD]; reused later as z3v
    float* z2v = sm + N_FEAT*PAD;       // [256][PAD]
    float* z2p = z2v + HID*PAD;
    float* z3p = z2p + HID*PAD;
    float* z3v = z1;

    const int t    = threadIdx.x;
    const int lane = t & 15;
    const int grp  = t >> 4;            // row within tile
    const long rowBase = (long)blockIdx.x * TILE;
    const long rowG    = rowBase + grp;
    const long rowLd   = rowG < N ? rowG : (long)N - 1;
    const bool rowOk   = rowG < N;

    // ---- load x tile (transposed into smem) + LN1 (standardize only) ----
    {
        const float* c0 = cum  + rowLd * 146;
        const float* f0 = feat + rowLd * 136;
        const float* p0 = pos  + rowLd * 10;
        float s = 0.f, ss = 0.f;
        for (int k = lane; k < N_FEAT; k += 16) {
            float x;
            if (k < 146)      x = c0[k];
            else if (k < 282) x = f0[k - 146];
            else              x = p0[k - 282];
            z1[k*PAD + grp] = x;
            s += x; ss += x * x;
        }
        #pragma unroll
        for (int o = 8; o; o >>= 1) {
            s  += __shfl_xor_sync(0xffffffffu, s,  o, 16);
            ss += __shfl_xor_sync(0xffffffffu, ss, o, 16);
        }
        const float inv = 1.f / (float)N_FEAT;
        float m    = s * inv;
        float var  = fmaxf(ss * inv - m*m, 0.f);
        float rstd = rsqrtf(var + 1e-5f);
        for (int k = lane; k < N_FEAT; k += 16)
            z1[k*PAD + grp] = (z1[k*PAD + grp] - m) * rstd;
    }
    __syncthreads();

    // ---- GEMM1: [16 x 292] @ [292 x 512], f32x2-packed rows ----
    {
        unsigned long long av[8], ap[8];
        #pragma unroll
        for (int i = 0; i < 8; i++) { av[i] = 0ull; ap[i] = 0ull; }
        const float4* Av = ((const float4*)g_A1v) + t;
        const float4* Ap = ((const float4*)g_A1p) + t;
        #pragma unroll 2
        for (int k4 = 0; k4 < N_FEAT/4; k4++) {
            float4 wv4 = Av[k4*HID];
            float4 wp4 = Ap[k4*HID];
            float wva[4]; *(float4*)wva = wv4;
            float wpa[4]; *(float4*)wpa = wp4;
            #pragma unroll
            for (int j = 0; j < 4; j++) {
                const float* zrow = z1 + (k4*4 + j)*PAD;
                unsigned long long wvv = pack2(wva[j]);
                unsigned long long wpp = pack2(wpa[j]);
                fma2x8(av, zrow, wvv);
                fma2x8(ap, zrow, wpp);
            }
        }
        const float b1v = g_c1v[t], b1p = g_c1p[t];
        #pragma unroll
        for (int i = 0; i < 8; i++) {
            float lo, hi;
            unpack2(av[i], lo, hi);
            z2v[t*PAD + 2*i]   = fmaxf(lo + b1v, 0.f);
            z2v[t*PAD + 2*i+1] = fmaxf(hi + b1v, 0.f);
            unpack2(ap[i], lo, hi);
            z2p[t*PAD + 2*i]   = fmaxf(lo + b1p, 0.f);
            z2p[t*PAD + 2*i+1] = fmaxf(hi + b1p, 0.f);
        }
    }
    __syncthreads();

    ln_rows(z2v, HID, lane, grp);
    ln_rows(z2p, HID, lane, grp);
    __syncthreads();

    // ---- GEMM2: [16 x 256] @ [256 x 512], f32x2-packed rows ----
    {
        unsigned long long av[8], ap[8];
        #pragma unroll
        for (int i = 0; i < 8; i++) { av[i] = 0ull; ap[i] = 0ull; }
        const float4* Av = ((const float4*)g_A2v) + t;
        const float4* Ap = ((const float4*)g_A2p) + t;
        #pragma unroll 2
        for (int k4 = 0; k4 < HID/4; k4++) {
            float4 wv4 = Av[k4*HID];
            float4 wp4 = Ap[k4*HID];
            float wva[4]; *(float4*)wva = wv4;
            float wpa[4]; *(float4*)wpa = wp4;
            #pragma unroll
            for (int j = 0; j < 4; j++) {
                const int k = k4*4 + j;
                unsigned long long wvv = pack2(wva[j]);
                unsigned long long wpp = pack2(wpa[j]);
                fma2x8(av, z2v + k*PAD, wvv);
                fma2x8(ap, z2p + k*PAD, wpp);
            }
        }
        const float b2v = g_c2v[t], b2p = g_c2p[t];
        // z3v aliases z1: safe, all z1 reads done before post-GEMM1 barrier
        #pragma unroll
        for (int i = 0; i < 8; i++) {
            float lo, hi;
            unpack2(av[i], lo, hi);
            z3v[t*PAD + 2*i]   = fmaxf(lo + b2v, 0.f);
            z3v[t*PAD + 2*i+1] = fmaxf(hi + b2v, 0.f);
            unpack2(ap[i], lo, hi);
            z3p[t*PAD + 2*i]   = fmaxf(lo + b2p, 0.f);
            z3p[t*PAD + 2*i+1] = fmaxf(hi + b2p, 0.f);
        }
    }
    __syncthreads();

    ln_rows(z3v, HID, lane, grp);
    ln_rows(z3p, HID, lane, grp);
    __syncthreads();

    // ---- heads: value = a3.z3v + c3 ; score = A3p^T z3p ; log_softmax ----
    {
        float s = 0.f;
        for (int k = lane; k < HID; k += 16)
            s += g_a3v[k] * z3v[k*PAD + grp];
        #pragma unroll
        for (int o = 8; o; o >>= 1)
            s += __shfl_xor_sync(0xffffffffu, s, o, 16);

        float acc[10];
        #pragma unroll
        for (int j = 0; j < 10; j++) acc[j] = 0.f;
        for (int k = lane; k < HID; k += 16) {
            float z = z3p[k*PAD + grp];
            #pragma unroll
            for (int j = 0; j < 10; j++)
                acc[j] = fmaf(z, g_A3p[k*10 + j], acc[j]);
        }
        #pragma unroll
        for (int j = 0; j < 10; j++) {
            #pragma unroll
            for (int o = 8; o; o >>= 1)
                acc[j] += __shfl_xor_sync(0xffffffffu, acc[j], o, 16);
        }

        if (lane == 0 && rowOk) {
            out[rowG] = s + g_c3v;                           // value [N]
            float sc[10];
            float mx = -3.4e38f;
            #pragma unroll
            for (int j = 0; j < 10; j++) {
                sc[j] = acc[j] + g_c3p[j];
                mx = fmaxf(mx, sc[j]);
            }
            float se = 0.f;
            #pragma unroll
            for (int j = 0; j < 10; j++) se += expf(sc[j] - mx);
            float lse = mx + logf(se);
            float* lp = out + N + rowG * 10;                 // log_prob [N,10]
            float* so = out + N + (long)N * 10 + rowG * 10;  // score [N,10]
            #pragma unroll
            for (int j = 0; j < 10; j++) {
                lp[j] = sc[j] - lse;
                so[j] = sc[j];
            }
        }
    }
}

// ---------------------------------------------------------------------------
extern "C" void kernel_launch(void* const* d_in, const int* in_sizes, int n_in,
                              void* d_out, int out_size) {
    const float* cum  = (const float*)d_in[0];
    const float* feat = (const float*)d_in[1];
    const float* pos  = (const float*)d_in[2];
    const int N = in_sizes[0] / 146;

    cudaFuncSetAttribute(bcq_main, cudaFuncAttributeMaxDynamicSharedMemorySize, SMEM_BYTES);

    prep_kernel<<<1025, 256>>>(
        (const float*)d_in[3],  (const float*)d_in[4],
        (const float*)d_in[5],  (const float*)d_in[6],
        (const float*)d_in[7],  (const float*)d_in[8],
        (const float*)d_in[9],  (const float*)d_in[10],
        (const float*)d_in[11], (const float*)d_in[12],
        (const float*)d_in[13], (const float*)d_in[14],
        (const float*)d_in[15], (const float*)d_in[16],
        (const float*)d_in[17], (const float*)d_in[18],
        (const float*)d_in[19], (const float*)d_in[20],
        (const float*)d_in[21], (const float*)d_in[22],
        (const float*)d_in[23], (const float*)d_in[24],
        (const float*)d_in[25], (const float*)d_in[26]);

    const int grid = (N + TILE - 1) / TILE;
    bcq_main<<<grid, 256, SMEM_BYTES>>>(cum, feat, pos, (float*)d_out, N);
}

// round 6
// speedup vs baseline: 1.6144x; 1.0973x over previous
#include <cuda_runtime.h>

#define N_FEAT 292
#define HID 256
#define TILE 16
#define PAD 20
#define SMEM_FLOATS (N_FEAT*PAD + 3*HID*PAD)
#define SMEM_BYTES (SMEM_FLOATS * 4)

// -------- gamma/beta-folded weights, k-packed: A[((k>>2)*HID + n)*4 + (k&3)]
__device__ float g_A1v[N_FEAT*HID];
__device__ float g_A1p[N_FEAT*HID];
__device__ float g_A2v[HID*HID];
__device__ float g_A2p[HID*HID];
__device__ float g_c1v[HID], g_c1p[HID], g_c2v[HID], g_c2p[HID];
__device__ float g_a3v[HID];
__device__ float g_A3p[HID*10];
__device__ float g_c3v;
__device__ float g_c3p[10];

// ---------------------------------------------------------------------------
// f32x2 helpers
// ---------------------------------------------------------------------------
__device__ __forceinline__ unsigned long long pack2(float w) {
    unsigned long long r;
    asm("mov.b64 %0, {%1, %1};" : "=l"(r) : "f"(w));
    return r;
}
__device__ __forceinline__ void unpack2(unsigned long long v, float& lo, float& hi) {
    asm("mov.b64 {%0, %1}, %2;" : "=f"(lo), "=f"(hi) : "l"(v));
}
__device__ __forceinline__ void fma2(unsigned long long& acc,
                                     unsigned long long z, unsigned long long w) {
    asm("fma.rn.f32x2 %0, %1, %2, %0;" : "+l"(acc) : "l"(z), "l"(w));
}
// 4 packed FMAs for one column over 8 rows (4 row-pairs)
__device__ __forceinline__ void fma2x4(unsigned long long* acc,
                                       const ulonglong2& zA, const ulonglong2& zB,
                                       unsigned long long w2) {
    fma2(acc[0], zA.x, w2); fma2(acc[1], zA.y, w2);
    fma2(acc[2], zB.x, w2); fma2(acc[3], zB.y, w2);
}

// ---------------------------------------------------------------------------
// Prep (unchanged layout)
// ---------------------------------------------------------------------------
__global__ void prep_kernel(
    const float* __restrict__ ln1_w, const float* __restrict__ ln1_b,
    const float* __restrict__ ln2_w, const float* __restrict__ ln2_b,
    const float* __restrict__ ln3_w, const float* __restrict__ ln3_b,
    const float* __restrict__ n1g,  const float* __restrict__ n1b,
    const float* __restrict__ n2g,  const float* __restrict__ n2b,
    const float* __restrict__ n3g,  const float* __restrict__ n3b,
    const float* __restrict__ p1w,  const float* __restrict__ p1b,
    const float* __restrict__ p2w,  const float* __restrict__ p2b,
    const float* __restrict__ p3w,  const float* __restrict__ p3b,
    const float* __restrict__ pn1g, const float* __restrict__ pn1b,
    const float* __restrict__ pn2g, const float* __restrict__ pn2b,
    const float* __restrict__ pn3g, const float* __restrict__ pn3b)
{
    __shared__ float red[256];
    const int b = blockIdx.x, t = threadIdx.x;

    if (b < 512) {
        const int tower = b >> 8, n = b & 255;
        const float* W  = tower ? p1w  : ln1_w;
        const float* bi = tower ? p1b  : ln1_b;
        const float* g  = tower ? pn1g : n1g;
        const float* be = tower ? pn1b : n1b;
        float* A = tower ? g_A1p : g_A1v;
        float* c = tower ? g_c1p : g_c1v;
        float s = 0.f;
        for (int k = t; k < N_FEAT; k += 256) {
            float w = W[n*N_FEAT + k];
            A[((k>>2)*HID + n)*4 + (k&3)] = w * g[k];
            s += w * be[k];
        }
        red[t] = s; __syncthreads();
        for (int o = 128; o > 0; o >>= 1) { if (t < o) red[t] += red[t+o]; __syncthreads(); }
        if (t == 0) c[n] = bi[n] + red[0];
    } else if (b < 1024) {
        const int idx = b - 512;
        const int tower = idx >> 8, n = idx & 255;
        const float* W  = tower ? p2w  : ln2_w;
        const float* bi = tower ? p2b  : ln2_b;
        const float* g  = tower ? pn2g : n2g;
        const float* be = tower ? pn2b : n2b;
        float* A = tower ? g_A2p : g_A2v;
        float* c = tower ? g_c2p : g_c2v;
        float w = W[n*HID + t];
        A[((t>>2)*HID + n)*4 + (t&3)] = w * g[t];
        red[t] = w * be[t]; __syncthreads();
        for (int o = 128; o > 0; o >>= 1) { if (t < o) red[t] += red[t+o]; __syncthreads(); }
        if (t == 0) c[n] = bi[n] + red[0];
    } else {
        float w3 = ln3_w[t];
        g_a3v[t] = w3 * n3g[t];
        red[t] = w3 * n3b[t]; __syncthreads();
        for (int o = 128; o > 0; o >>= 1) { if (t < o) red[t] += red[t+o]; __syncthreads(); }
        if (t == 0) g_c3v = ln3_b[0] + red[0];
        __syncthreads();
        #pragma unroll
        for (int j = 0; j < 10; j++)
            g_A3p[t*10 + j] = p3w[j*HID + t] * pn3g[t];
        for (int j = 0; j < 10; j++) {
            red[t] = p3w[j*HID + t] * pn3b[t]; __syncthreads();
            for (int o = 128; o > 0; o >>= 1) { if (t < o) red[t] += red[t+o]; __syncthreads(); }
            if (t == 0) g_c3p[j] = p3b[j] + red[0];
            __syncthreads();
        }
    }
}

// ---------------------------------------------------------------------------
// Main fused kernel
// ---------------------------------------------------------------------------
__device__ __forceinline__ void ln_rows(float* z, int K, int lane, int r) {
    float s = 0.f, ss = 0.f;
    for (int k = lane; k < K; k += 16) {
        float x = z[k*PAD + r];
        s += x; ss += x * x;
    }
    #pragma unroll
    for (int o = 8; o; o >>= 1) {
        s  += __shfl_xor_sync(0xffffffffu, s,  o, 16);
        ss += __shfl_xor_sync(0xffffffffu, ss, o, 16);
    }
    const float inv = 1.f / (float)K;
    float m    = s * inv;
    float var  = fmaxf(ss * inv - m*m, 0.f);
    float rstd = rsqrtf(var + 1e-5f);
    for (int k = lane; k < K; k += 16)
        z[k*PAD + r] = (z[k*PAD + r] - m) * rstd;
}

__global__ __launch_bounds__(256, 2) void bcq_main(
    const float* __restrict__ cum, const float* __restrict__ feat,
    const float* __restrict__ pos, float* __restrict__ out, int N)
{
    extern __shared__ float sm[];
    float* z1  = sm;                    // [292][PAD]; reused later as z3v
    float* z2v = sm + N_FEAT*PAD;       // [256][PAD]
    float* z2p = z2v + HID*PAD;
    float* z3p = z2p + HID*PAD;
    float* z3v = z1;

    const int t    = threadIdx.x;
    const int lane = t & 15;
    const int grp  = t >> 4;
    const int half = t >> 7;            // 0: rows 0-7, 1: rows 8-15
    const int rOff = half * 8;
    const int n0   = t & 127;           // owned columns per tower: n0, n0+128
    const int n1   = n0 + 128;
    const long rowBase = (long)blockIdx.x * TILE;
    const long rowG    = rowBase + grp;
    const long rowLd   = rowG < N ? rowG : (long)N - 1;
    const bool rowOk   = rowG < N;

    // ---- load x tile (transposed into smem) + LN1 (standardize only) ----
    {
        const float* c0 = cum  + rowLd * 146;
        const float* f0 = feat + rowLd * 136;
        const float* p0 = pos  + rowLd * 10;
        float s = 0.f, ss = 0.f;
        for (int k = lane; k < N_FEAT; k += 16) {
            float x;
            if (k < 146)      x = c0[k];
            else if (k < 282) x = f0[k - 146];
            else              x = p0[k - 282];
            z1[k*PAD + grp] = x;
            s += x; ss += x * x;
        }
        #pragma unroll
        for (int o = 8; o; o >>= 1) {
            s  += __shfl_xor_sync(0xffffffffu, s,  o, 16);
            ss += __shfl_xor_sync(0xffffffffu, ss, o, 16);
        }
        const float inv = 1.f / (float)N_FEAT;
        float m    = s * inv;
        float var  = fmaxf(ss * inv - m*m, 0.f);
        float rstd = rsqrtf(var + 1e-5f);
        for (int k = lane; k < N_FEAT; k += 16)
            z1[k*PAD + grp] = (z1[k*PAD + grp] - m) * rstd;
    }
    __syncthreads();

    // ---- GEMM1: 8 rows x {n0,n1} x 2 towers; z shared by all 4 columns ----
    {
        unsigned long long av0[4], av1[4], ap0[4], ap1[4];
        #pragma unroll
        for (int i = 0; i < 4; i++) { av0[i]=0ull; av1[i]=0ull; ap0[i]=0ull; ap1[i]=0ull; }
        const float4* Wv = (const float4*)g_A1v;
        const float4* Wp = (const float4*)g_A1p;
        #pragma unroll 2
        for (int k4 = 0; k4 < N_FEAT/4; k4++) {
            float4 wv0 = Wv[k4*HID + n0];
            float4 wv1 = Wv[k4*HID + n1];
            float4 wp0 = Wp[k4*HID + n0];
            float4 wp1 = Wp[k4*HID + n1];
            float av0a[4]; *(float4*)av0a = wv0;
            float av1a[4]; *(float4*)av1a = wv1;
            float ap0a[4]; *(float4*)ap0a = wp0;
            float ap1a[4]; *(float4*)ap1a = wp1;
            #pragma unroll
            for (int j = 0; j < 4; j++) {
                const ulonglong2* zr = (const ulonglong2*)(z1 + (k4*4+j)*PAD + rOff);
                ulonglong2 zA = zr[0], zB = zr[1];
                fma2x4(av0, zA, zB, pack2(av0a[j]));
                fma2x4(av1, zA, zB, pack2(av1a[j]));
                fma2x4(ap0, zA, zB, pack2(ap0a[j]));
                fma2x4(ap1, zA, zB, pack2(ap1a[j]));
            }
        }
        const float b_v0 = g_c1v[n0], b_v1 = g_c1v[n1];
        const float b_p0 = g_c1p[n0], b_p1 = g_c1p[n1];
        #pragma unroll
        for (int i = 0; i < 4; i++) {
            float lo, hi;
            unpack2(av0[i], lo, hi);
            z2v[n0*PAD + rOff + 2*i]   = fmaxf(lo + b_v0, 0.f);
            z2v[n0*PAD + rOff + 2*i+1] = fmaxf(hi + b_v0, 0.f);
            unpack2(av1[i], lo, hi);
            z2v[n1*PAD + rOff + 2*i]   = fmaxf(lo + b_v1, 0.f);
            z2v[n1*PAD + rOff + 2*i+1] = fmaxf(hi + b_v1, 0.f);
            unpack2(ap0[i], lo, hi);
            z2p[n0*PAD + rOff + 2*i]   = fmaxf(lo + b_p0, 0.f);
            z2p[n0*PAD + rOff + 2*i+1] = fmaxf(hi + b_p0, 0.f);
            unpack2(ap1[i], lo, hi);
            z2p[n1*PAD + rOff + 2*i]   = fmaxf(lo + b_p1, 0.f);
            z2p[n1*PAD + rOff + 2*i+1] = fmaxf(hi + b_p1, 0.f);
        }
    }
    __syncthreads();

    ln_rows(z2v, HID, lane, grp);
    ln_rows(z2p, HID, lane, grp);
    __syncthreads();

    // ---- GEMM2: same blocking; per-tower activations ----
    {
        unsigned long long av0[4], av1[4], ap0[4], ap1[4];
        #pragma unroll
        for (int i = 0; i < 4; i++) { av0[i]=0ull; av1[i]=0ull; ap0[i]=0ull; ap1[i]=0ull; }
        const float4* Wv = (const float4*)g_A2v;
        const float4* Wp = (const float4*)g_A2p;
        #pragma unroll 2
        for (int k4 = 0; k4 < HID/4; k4++) {
            float4 wv0 = Wv[k4*HID + n0];
            float4 wv1 = Wv[k4*HID + n1];
            float4 wp0 = Wp[k4*HID + n0];
            float4 wp1 = Wp[k4*HID + n1];
            float av0a[4]; *(float4*)av0a = wv0;
            float av1a[4]; *(float4*)av1a = wv1;
            float ap0a[4]; *(float4*)ap0a = wp0;
            float ap1a[4]; *(float4*)ap1a = wp1;
            #pragma unroll
            for (int j = 0; j < 4; j++) {
                const int k = k4*4 + j;
                const ulonglong2* zrv = (const ulonglong2*)(z2v + k*PAD + rOff);
                ulonglong2 zvA = zrv[0], zvB = zrv[1];
                fma2x4(av0, zvA, zvB, pack2(av0a[j]));
                fma2x4(av1, zvA, zvB, pack2(av1a[j]));
                const ulonglong2* zrp = (const ulonglong2*)(z2p + k*PAD + rOff);
                ulonglong2 zpA = zrp[0], zpB = zrp[1];
                fma2x4(ap0, zpA, zpB, pack2(ap0a[j]));
                fma2x4(ap1, zpA, zpB, pack2(ap1a[j]));
            }
        }
        const float b_v0 = g_c2v[n0], b_v1 = g_c2v[n1];
        const float b_p0 = g_c2p[n0], b_p1 = g_c2p[n1];
        // z3v aliases z1: safe, all z1 reads done before post-GEMM1 barrier
        #pragma unroll
        for (int i = 0; i < 4; i++) {
            float lo, hi;
            unpack2(av0[i], lo, hi);
            z3v[n0*PAD + rOff + 2*i]   = fmaxf(lo + b_v0, 0.f);
            z3v[n0*PAD + rOff + 2*i+1] = fmaxf(hi + b_v0, 0.f);
            unpack2(av1[i], lo, hi);
            z3v[n1*PAD + rOff + 2*i]   = fmaxf(lo + b_v1, 0.f);
            z3v[n1*PAD + rOff + 2*i+1] = fmaxf(hi + b_v1, 0.f);
            unpack2(ap0[i], lo, hi);
            z3p[n0*PAD + rOff + 2*i]   = fmaxf(lo + b_p0, 0.f);
            z3p[n0*PAD + rOff + 2*i+1] = fmaxf(hi + b_p0, 0.f);
            unpack2(ap1[i], lo, hi);
            z3p[n1*PAD + rOff + 2*i]   = fmaxf(lo + b_p1, 0.f);
            z3p[n1*PAD + rOff + 2*i+1] = fmaxf(hi + b_p1, 0.f);
        }
    }
    __syncthreads();

    ln_rows(z3v, HID, lane, grp);
    ln_rows(z3p, HID, lane, grp);
    __syncthreads();

    // ---- heads ----
    {
        float s = 0.f;
        for (int k = lane; k < HID; k += 16)
            s += g_a3v[k] * z3v[k*PAD + grp];
        #pragma unroll
        for (int o = 8; o; o >>= 1)
            s += __shfl_xor_sync(0xffffffffu, s, o, 16);

        float acc[10];
        #pragma unroll
        for (int j = 0; j < 10; j++) acc[j] = 0.f;
        for (int k = lane; k < HID; k += 16) {
            float z = z3p[k*PAD + grp];
            #pragma unroll
            for (int j = 0; j < 10; j++)
                acc[j] = fmaf(z, g_A3p[k*10 + j], acc[j]);
        }
        #pragma unroll
        for (int j = 0; j < 10; j++) {
            #pragma unroll
            for (int o = 8; o; o >>= 1)
                acc[j] += __shfl_xor_sync(0xffffffffu, acc[j], o, 16);
        }

        if (lane == 0 && rowOk) {
            out[rowG] = s + g_c3v;                           // value [N]
            float sc[10];
            float mx = -3.4e38f;
            #pragma unroll
            for (int j = 0; j < 10; j++) {
                sc[j] = acc[j] + g_c3p[j];
                mx = fmaxf(mx, sc[j]);
            }
            float se = 0.f;
            #pragma unroll
            for (int j = 0; j < 10; j++) se += expf(sc[j] - mx);
            float lse = mx + logf(se);
            float* lp = out + N + rowG * 10;                 // log_prob [N,10]
            float* so = out + N + (long)N * 10 + rowG * 10;  // score [N,10]
            #pragma unroll
            for (int j = 0; j < 10; j++) {
                lp[j] = sc[j] - lse;
                so[j] = sc[j];
            }
        }
    }
}

// ---------------------------------------------------------------------------
extern "C" void kernel_launch(void* const* d_in, const int* in_sizes, int n_in,
                              void* d_out, int out_size) {
    const float* cum  = (const float*)d_in[0];
    const float* feat = (const float*)d_in[1];
    const float* pos  = (const float*)d_in[2];
    const int N = in_sizes[0] / 146;

    cudaFuncSetAttribute(bcq_main, cudaFuncAttributeMaxDynamicSharedMemorySize, SMEM_BYTES);

    prep_kernel<<<1025, 256>>>(
        (const float*)d_in[3],  (const float*)d_in[4],
        (const float*)d_in[5],  (const float*)d_in[6],
        (const float*)d_in[7],  (const float*)d_in[8],
        (const float*)d_in[9],  (const float*)d_in[10],
        (const float*)d_in[11], (const float*)d_in[12],
        (const float*)d_in[13], (const float*)d_in[14],
        (const float*)d_in[15], (const float*)d_in[16],
        (const float*)d_in[17], (const float*)d_in[18],
        (const float*)d_in[19], (const float*)d_in[20],
        (const float*)d_in[21], (const float*)d_in[22],
        (const float*)d_in[23], (const float*)d_in[24],
        (const float*)d_in[25], (const float*)d_in[26]);

    const int grid = (N + TILE - 1) / TILE;
    bcq_main<<<grid, 256, SMEM_BYTES>>>(cum, feat, pos, (float*)d_out, N);
}